// round 7
// baseline (speedup 1.0000x reference)
#include <cuda_runtime.h>
#include <cuda_fp16.h>
#include <cstdint>
#include <math.h>

#define DEPTH 16
#define NN    65535
#define H     256
#define KIN   768
#define NCOL  1280           // 5 gates * 256 units, col = j*5+g

// ---------------- device scratch (no cudaMalloc allowed) ----------------
__device__ __half g_ehi[(size_t)NN * H];
__device__ __half g_elo[(size_t)NN * H];
__device__ __half g_hhi[(size_t)NN * H];
__device__ __half g_hlo[(size_t)NN * H];
__device__ float  g_c  [(size_t)NN * H];
__device__ __half g_B  [(size_t)NCOL * KIN];   // [col][k], fp16
__device__ float  g_bias[NCOL];

// ---------------- smem layouts ----------------
// Main: A' stage 256 rows x 144B, B stage 80 x 144B, 2 stages.
static constexpr int ASTG = 256 * 144;                     // 36864
static constexpr int BSTG = 80 * 144;                      // 11520
static constexpr int OFF_BS_MAIN = 2 * ASTG;               // 73728
static constexpr int SMEM_MAIN   = 2 * ASTG + 2 * BSTG;    // 96768
// Small: per (slice, stage): A' 64x144 + B 80x144.
static constexpr int SLST = 64 * 144 + 80 * 144;           // 20736
static constexpr int SMEM_SMALL = 8 * SLST;                // 165888

// ---------------- PTX helpers (baseline sm_80+) ----------------
__device__ __forceinline__ uint32_t smem_to_u32(const void* p) {
    uint32_t a;
    asm("{ .reg .u64 t; cvta.to.shared.u64 t, %1; cvt.u32.u64 %0, t; }" : "=r"(a) : "l"(p));
    return a;
}
__device__ __forceinline__ void cpasync16(uint32_t dst, const void* src) {
    asm volatile("cp.async.cg.shared.global [%0], [%1], 16;" :: "r"(dst), "l"(src) : "memory");
}
#define CP_COMMIT() asm volatile("cp.async.commit_group;" ::: "memory")
#define CP_WAIT(N)  asm volatile("cp.async.wait_group %0;" :: "n"(N) : "memory")

__device__ __forceinline__ void ldsm4(uint32_t* r, uint32_t addr) {
    asm volatile("ldmatrix.sync.aligned.m8n8.x4.shared.b16 {%0,%1,%2,%3}, [%4];"
        : "=r"(r[0]), "=r"(r[1]), "=r"(r[2]), "=r"(r[3]) : "r"(addr));
}
__device__ __forceinline__ void ldsm2(uint32_t* r, uint32_t addr) {
    asm volatile("ldmatrix.sync.aligned.m8n8.x2.shared.b16 {%0,%1}, [%2];"
        : "=r"(r[0]), "=r"(r[1]) : "r"(addr));
}
__device__ __forceinline__ void mma16816(float* d, const uint32_t* a, const uint32_t* b) {
    asm volatile("mma.sync.aligned.m16n8k16.row.col.f32.f16.f16.f32 "
        "{%0,%1,%2,%3}, {%4,%5,%6,%7}, {%8,%9}, {%0,%1,%2,%3};"
        : "+f"(d[0]), "+f"(d[1]), "+f"(d[2]), "+f"(d[3])
        : "r"(a[0]), "r"(a[1]), "r"(a[2]), "r"(a[3]), "r"(b[0]), "r"(b[1]));
}

__device__ __forceinline__ float sigmoidf_(float x) { return 1.f / (1.f + expf(-x)); }

// One KT=64 chunk of warp-tile MMA: A rows [wm, wm+32), B rows [wn, wn+40).
__device__ __forceinline__ void chunk_mma(uint32_t abuf, uint32_t bbuf,
                                          int wm, int wn, int lane,
                                          float acc[2][5][4]) {
#pragma unroll
    for (int k16 = 0; k16 < 4; ++k16) {
        const int kb = k16 * 16;
        uint32_t a[2][4], b[5][2];
#pragma unroll
        for (int mt = 0; mt < 2; ++mt) {
            uint32_t addr = abuf + (wm + mt * 16 + (lane & 15)) * 144
                          + (kb + ((lane >> 4) << 3)) * 2;
            ldsm4(a[mt], addr);
        }
#pragma unroll
        for (int p = 0; p < 2; ++p) {
            uint32_t r[4];
            uint32_t addr = bbuf
                + (wn + p * 16 + ((lane >> 4) << 3) + (lane & 7)) * 144
                + (kb + (((lane >> 3) & 1) << 3)) * 2;
            ldsm4(r, addr);
            b[p * 2 + 0][0] = r[0]; b[p * 2 + 0][1] = r[1];
            b[p * 2 + 1][0] = r[2]; b[p * 2 + 1][1] = r[3];
        }
        {
            uint32_t addr = bbuf + (wn + 32 + (lane & 7)) * 144
                          + (kb + (((lane >> 3) & 1) << 3)) * 2;
            ldsm2(b[4], addr);
        }
#pragma unroll
        for (int mt = 0; mt < 2; ++mt)
#pragma unroll
            for (int nt = 0; nt < 5; ++nt)
                mma16816(acc[mt][nt], a[mt], b[nt]);
    }
}

// ---------------- pack kernels ----------------
__global__ void split_emb_kernel(const float* __restrict__ emb) {
    int idx = blockIdx.x * blockDim.x + threadIdx.x;
    int stride = gridDim.x * blockDim.x;
    const int total4 = (NN * H) / 4;
    for (int i = idx; i < total4; i += stride) {
        float4 v = reinterpret_cast<const float4*>(emb)[i];
        __half hh[4], hl[4];
        float f[4] = {v.x, v.y, v.z, v.w};
#pragma unroll
        for (int k = 0; k < 4; ++k) {
            hh[k] = __float2half(f[k]);
            hl[k] = __float2half(f[k] - __half2float(hh[k]));
        }
        reinterpret_cast<uint2*>(g_ehi)[i] = *reinterpret_cast<uint2*>(hh);
        reinterpret_cast<uint2*>(g_elo)[i] = *reinterpret_cast<uint2*>(hl);
    }
}

__global__ void pack_w_kernel(
    const float* __restrict__ Wi, const float* __restrict__ bi, const float* __restrict__ Ui,
    const float* __restrict__ Wo, const float* __restrict__ bo, const float* __restrict__ Uo,
    const float* __restrict__ Wu, const float* __restrict__ bu, const float* __restrict__ Uu,
    const float* __restrict__ Wf, const float* __restrict__ bf, const float* __restrict__ Uf)
{
    int idx = blockIdx.x * blockDim.x + threadIdx.x;
    int stride = gridDim.x * blockDim.x;
    if (idx < NCOL) {
        int j = idx / 5, g = idx % 5;
        g_bias[idx] = (g == 0) ? bi[j] : (g == 1) ? bo[j] : (g == 2) ? bu[j] : bf[j];
    }
    for (int e = idx; e < NCOL * KIN; e += stride) {
        int col = e / KIN;
        int k   = e - col * KIN;
        int j = col / 5, g = col % 5;
        float v = 0.f;
        if (k < H) {
            const float* W = (g == 0) ? Wi : (g == 1) ? Wo : (g == 2) ? Wu : Wf;
            v = W[j * H + k];
        } else if (k < 2 * H) {
            int kk = k - H;
            if      (g == 0) v = Ui[j * H + kk];
            else if (g == 1) v = Uo[j * H + kk];
            else if (g == 2) v = Uu[j * H + kk];
            else if (g == 3) v = Uf[j * H + kk];
        } else {
            int kk = k - 2 * H;
            if      (g == 0) v = Ui[H * H + j * H + kk];
            else if (g == 1) v = Uo[H * H + j * H + kk];
            else if (g == 2) v = Uu[H * H + j * H + kk];
            else if (g == 4) v = Uf[H * H + j * H + kk];
        }
        g_B[e] = __float2half(v);
    }
}

// ---------------- main level kernel ----------------
// A' = [A_hi ; A_lo] stacked along M: 256 rows = 128 nodes x {hi,lo}. K = KIN.
// Block: 512 threads = 16 warps (8 m-slices x 2 n-halves), tile 256 x 80.
template <bool HASCH>
__global__ void __launch_bounds__(512, 1) hmma_level_kernel(
    int start, int n, float* __restrict__ out)
{
    extern __shared__ char smem[];
    const uint32_t sbase = smem_to_u32(smem);

    const int t    = threadIdx.x;
    const int lane = t & 31;
    const int wid  = t >> 5;
    const int cb   = blockIdx.x;          // 0..15 column blocks (80 cols each)
    const int m0   = blockIdx.y * 128;
    const int gn0  = start + m0;
    const int col0 = cb * 80;

    constexpr int NCH = HASCH ? (KIN / 64) : (H / 64);   // 12 / 4

    float acc[2][5][4];
#pragma unroll
    for (int mt = 0; mt < 2; ++mt)
#pragma unroll
        for (int nt = 0; nt < 5; ++nt)
#pragma unroll
            for (int r = 0; r < 4; ++r) acc[mt][nt][r] = 0.f;

    auto load_chunk = [&](int c, int st) {
        const int k0 = c * 64;
        const __half* ahi;
        const __half* alo;
        int astride;
        if (!HASCH || k0 < H) {
            ahi = g_ehi + (size_t)gn0 * H + k0;
            alo = g_elo + (size_t)gn0 * H + k0;
            astride = H;
        } else if (k0 < 2 * H) {
            ahi = g_hhi + (size_t)(2 * gn0 + 1) * H + (k0 - H);
            alo = g_hlo + (size_t)(2 * gn0 + 1) * H + (k0 - H);
            astride = 2 * H;
        } else {
            ahi = g_hhi + (size_t)(2 * gn0 + 2) * H + (k0 - 2 * H);
            alo = g_hlo + (size_t)(2 * gn0 + 2) * H + (k0 - 2 * H);
            astride = 2 * H;
        }
        const __half* bbase = g_B + (size_t)col0 * KIN + k0;
        const uint32_t adst = sbase + st * ASTG;
        const uint32_t bdst = sbase + OFF_BS_MAIN + st * BSTG;
#pragma unroll
        for (int i = 0; i < 6; ++i) {
            int idx = t + i * 512;
            if (idx < 2048) {                       // A': 256 rows x 8 segs
                int row = idx >> 3, seg = idx & 7;
                int arow = row & 127;
                const __half* src = (row < 128 ? ahi : alo) + (size_t)arow * astride + seg * 8;
                cpasync16(adst + row * 144 + seg * 16, src);
            } else if (idx < 2688) {                // B: 80 rows x 8 segs
                int r2 = idx - 2048;
                int row = r2 >> 3, seg = r2 & 7;
                cpasync16(bdst + row * 144 + seg * 16,
                          bbase + (size_t)row * KIN + seg * 8);
            }
        }
        CP_COMMIT();
    };

    load_chunk(0, 0);

    const int wm = (wid & 7) * 32;
    const int wn = (wid >> 3) * 40;

    for (int c = 0; c < NCH; ++c) {
        const int st = c & 1;
        CP_WAIT(0);
        __syncthreads();
        if (c + 1 < NCH) load_chunk(c + 1, st ^ 1);
        chunk_mma(sbase + st * ASTG, sbase + OFF_BS_MAIN + st * BSTG,
                  wm, wn, lane, acc);
    }
    __syncthreads();             // protect stage smem before aliasing as Cs

    // ---- epilogue: frags -> smem C[256][84], combine hi+lo, gates ----
    float* Cs = reinterpret_cast<float*>(smem);
#pragma unroll
    for (int mt = 0; mt < 2; ++mt)
#pragma unroll
        for (int nt = 0; nt < 5; ++nt) {
            int m  = wm + mt * 16 + (lane >> 2);
            int nn = wn + nt * 8 + (lane & 3) * 2;
            Cs[m * 84 + nn]           = acc[mt][nt][0];
            Cs[m * 84 + nn + 1]       = acc[mt][nt][1];
            Cs[(m + 8) * 84 + nn]     = acc[mt][nt][2];
            Cs[(m + 8) * 84 + nn + 1] = acc[mt][nt][3];
        }
    __syncthreads();

#pragma unroll
    for (int pass = 0; pass < 4; ++pass) {
        const int task = t + pass * 512;      // 128 nodes x 16 units
        const int m = task >> 4;
        const int u = task & 15;
        if (m0 + m >= n) continue;
        const int gn = gn0 + m;
        const int j  = cb * 16 + u;

        const float* cpH = &Cs[m * 84 + u * 5];
        const float* cpL = &Cs[(m + 128) * 84 + u * 5];
        float zi = cpH[0] + cpL[0] + g_bias[j * 5 + 0];
        float zo = cpH[1] + cpL[1] + g_bias[j * 5 + 1];
        float zu = cpH[2] + cpL[2] + g_bias[j * 5 + 2];
        float vi = sigmoidf_(zi);
        float vo = sigmoidf_(zo);
        float vu = tanhf(zu);
        float cv = vi * vu;
        if (HASCH) {
            float zf0 = cpH[3] + cpL[3] + g_bias[j * 5 + 3];
            float zf1 = cpH[4] + cpL[4] + g_bias[j * 5 + 4];
            cv += sigmoidf_(zf0) * g_c[(size_t)(2 * gn + 1) * H + j]
                + sigmoidf_(zf1) * g_c[(size_t)(2 * gn + 2) * H + j];
        }
        float h = vo * tanhf(cv);
        __half hh = __float2half(h);
        g_hhi[(size_t)gn * H + j] = hh;
        g_hlo[(size_t)gn * H + j] = __float2half(h - __half2float(hh));
        g_c  [(size_t)gn * H + j] = cv;
        if (out != nullptr && gn == 0) {
            out[j]     = h;
            out[H + j] = cv;
        }
    }
}

// ---------------- small-level kernel: split-K x4, M-stacked, 512 threads ----------------
// 16 warps = 4 K-slices x 2 m-halves x 2 n-halves. M-tile 32 nodes -> A' 64 rows.
// Each K-slice: 3 chunks of KT=64 (K = 768). Internal levels only.
__global__ void __launch_bounds__(512, 1) smallk_kernel(int start, int n, float* __restrict__ out)
{
    extern __shared__ char smem[];
    const uint32_t sbase = smem_to_u32(smem);

    const int t    = threadIdx.x;
    const int lane = t & 31;
    const int wid  = t >> 5;
    const int cb   = blockIdx.x;
    const int m0   = blockIdx.y * 32;
    const int gn0  = start + m0;
    const int col0 = cb * 80;

    const int ks = wid >> 2;              // K-slice 0..3
    const int wm = ((wid >> 1) & 1) * 32; // m-half within 64 A'-rows
    const int wn = (wid & 1) * 40;        // n-half

    constexpr int PER = 3;                // chunks per slice (768 / 64 / 4)

    float acc[2][5][4];
#pragma unroll
    for (int mt = 0; mt < 2; ++mt)
#pragma unroll
        for (int nt = 0; nt < 5; ++nt)
#pragma unroll
            for (int r = 0; r < 4; ++r) acc[mt][nt][r] = 0.f;

    auto load_step = [&](int step, int st) {
#pragma unroll
        for (int i = 0; i < 9; ++i) {             // 4 slices x (512 A + 640 B) = 4608 ops
            int idx = t + i * 512;
            int sl  = idx / 1152;
            int rem = idx - sl * 1152;
            int c   = sl * PER + step;
            int k0  = c * 64;
            uint32_t sbuf = sbase + (sl * 2 + st) * SLST;
            if (rem < 512) {                      // A': 64 rows x 8 segs
                int row = rem >> 3, seg = rem & 7;
                int arow = row & 31;
                bool lo = row >= 32;
                const __half* src;
                if (k0 < H) {
                    src = (lo ? g_elo : g_ehi) + (size_t)(gn0 + arow) * H + k0;
                } else if (k0 < 2 * H) {
                    src = (lo ? g_hlo : g_hhi) + (size_t)(2 * (gn0 + arow) + 1) * H + (k0 - H);
                } else {
                    src = (lo ? g_hlo : g_hhi) + (size_t)(2 * (gn0 + arow) + 2) * H + (k0 - 2 * H);
                }
                cpasync16(sbuf + row * 144 + seg * 16, src + seg * 8);
            } else {                              // B: 80 rows x 8 segs
                int r2 = rem - 512;
                int row = r2 >> 3, seg = r2 & 7;
                cpasync16(sbuf + 64 * 144 + row * 144 + seg * 16,
                          g_B + (size_t)(col0 + row) * KIN + k0 + seg * 8);
            }
        }
        CP_COMMIT();
    };

    load_step(0, 0);

    for (int step = 0; step < PER; ++step) {
        const int st = step & 1;
        CP_WAIT(0);
        __syncthreads();
        if (step + 1 < PER) load_step(step + 1, st ^ 1);
        const uint32_t abuf = sbase + (ks * 2 + st) * SLST;
        chunk_mma(abuf, abuf + 64 * 144, wm, wn, lane, acc);
    }
    __syncthreads();

    // ---- reduce 4 K-slices + hi/lo through smem, then gates ----
    float* Cp = reinterpret_cast<float*>(smem);   // [4][64][84] = 86016 B
#pragma unroll
    for (int mt = 0; mt < 2; ++mt)
#pragma unroll
        for (int nt = 0; nt < 5; ++nt) {
            int m  = wm + mt * 16 + (lane >> 2);
            int nn = wn + nt * 8 + (lane & 3) * 2;
            float* dst = Cp + ks * (64 * 84);
            dst[m * 84 + nn]           = acc[mt][nt][0];
            dst[m * 84 + nn + 1]       = acc[mt][nt][1];
            dst[(m + 8) * 84 + nn]     = acc[mt][nt][2];
            dst[(m + 8) * 84 + nn + 1] = acc[mt][nt][3];
        }
    __syncthreads();

    {
        const int task = t;                       // 32 nodes x 16 units = 512
        const int m = task >> 4;
        const int u = task & 15;
        if (m0 + m < n) {
            const int gn = gn0 + m;
            const int j  = cb * 16 + u;
            float z[5];
#pragma unroll
            for (int g = 0; g < 5; ++g) {
                float s = g_bias[j * 5 + g];
#pragma unroll
                for (int sl = 0; sl < 4; ++sl)
                    s += Cp[sl * (64 * 84) + m * 84 + u * 5 + g]
                       + Cp[sl * (64 * 84) + (m + 32) * 84 + u * 5 + g];
                z[g] = s;
            }
            float vi = sigmoidf_(z[0]);
            float vo = sigmoidf_(z[1]);
            float vu = tanhf(z[2]);
            float cv = vi * vu
                     + sigmoidf_(z[3]) * g_c[(size_t)(2 * gn + 1) * H + j]
                     + sigmoidf_(z[4]) * g_c[(size_t)(2 * gn + 2) * H + j];
            float h = vo * tanhf(cv);
            __half hh = __float2half(h);
            g_hhi[(size_t)gn * H + j] = hh;
            g_hlo[(size_t)gn * H + j] = __float2half(h - __half2float(hh));
            g_c  [(size_t)gn * H + j] = cv;
            if (out != nullptr && gn == 0) {
                out[j]     = h;
                out[H + j] = cv;
            }
        }
    }
}

// ---------------- host launcher ----------------
extern "C" void kernel_launch(void* const* d_in, const int* in_sizes, int n_in,
                              void* d_out, int out_size)
{
    const float* emb = (const float*)d_in[0];
    const float* Wi  = (const float*)d_in[1];
    const float* bi  = (const float*)d_in[2];
    const float* Ui  = (const float*)d_in[3];
    const float* Wo  = (const float*)d_in[4];
    const float* bo  = (const float*)d_in[5];
    const float* Uo  = (const float*)d_in[6];
    const float* Wu  = (const float*)d_in[7];
    const float* bu  = (const float*)d_in[8];
    const float* Uu  = (const float*)d_in[9];
    const float* Wf  = (const float*)d_in[10];
    const float* bf  = (const float*)d_in[11];
    const float* Uf  = (const float*)d_in[12];

    cudaFuncSetAttribute(hmma_level_kernel<false>, cudaFuncAttributeMaxDynamicSharedMemorySize, SMEM_MAIN);
    cudaFuncSetAttribute(hmma_level_kernel<true>,  cudaFuncAttributeMaxDynamicSharedMemorySize, SMEM_MAIN);
    cudaFuncSetAttribute(smallk_kernel,            cudaFuncAttributeMaxDynamicSharedMemorySize, SMEM_SMALL);

    split_emb_kernel<<<2048, 256>>>(emb);
    pack_w_kernel<<<1024, 256>>>(Wi, bi, Ui, Wo, bo, Uo, Wu, bu, Uu, Wf, bf, Uf);

    // leaves: level 15, n = 32768, K = 256 (no children), NCH = 4
    {
        int n = 1 << (DEPTH - 1);
        int start = n - 1;
        dim3 grid(16, n / 128);
        hmma_level_kernel<false><<<grid, 512, SMEM_MAIN>>>(start, n, nullptr);
    }
    // internal levels bottom-up
    for (int l = DEPTH - 2; l >= 0; --l) {
        int n = 1 << l;
        int start = n - 1;
        float* outp = (l == 0) ? (float*)d_out : nullptr;
        if (n >= 1024) {
            dim3 grid(16, n / 128);
            hmma_level_kernel<true><<<grid, 512, SMEM_MAIN>>>(start, n, outp);
        } else {
            dim3 grid(16, (n + 31) / 32);
            smallk_kernel<<<grid, 512, SMEM_SMALL>>>(start, n, outp);
        }
    }
}

// round 8
// speedup vs baseline: 1.1604x; 1.1604x over previous
#include <cuda_runtime.h>
#include <cuda_fp16.h>
#include <cstdint>
#include <math.h>

#define DEPTH 16
#define NN    65535
#define H     256
#define KIN   768
#define NCOL  1280           // 5 gates * 256 units, col = j*5+g

// ---------------- device scratch (no cudaMalloc allowed) ----------------
__device__ __half g_ehi[(size_t)NN * H];
__device__ __half g_elo[(size_t)NN * H];
__device__ __half g_hhi[(size_t)NN * H];
__device__ __half g_hlo[(size_t)NN * H];
__device__ float  g_c  [(size_t)NN * H];
__device__ __half g_B  [(size_t)NCOL * KIN];   // [col][k], fp16 hi only
__device__ float  g_bias[NCOL];

// ---------------- smem layouts ----------------
// Main: 3 stages of (A 128x144B + B 80x144B).
static constexpr int ASTG = 128 * 144;                     // 18432
static constexpr int BSTG = 80 * 144;                      // 11520
static constexpr int OFF_BS_MAIN = 3 * ASTG;               // 55296
static constexpr int SMEM_MAIN   = 3 * (ASTG + BSTG);      // 89856
// Small kernel: per (slice, stage): A 32x144 + B 80x144, 4 slices x 2 stages.
static constexpr int SLST = 32 * 144 + 80 * 144;  // 16128
static constexpr int SMEM_SMALL = 8 * SLST;       // 129024

// ---------------- PTX helpers (baseline sm_80+) ----------------
__device__ __forceinline__ uint32_t smem_to_u32(const void* p) {
    uint32_t a;
    asm("{ .reg .u64 t; cvta.to.shared.u64 t, %1; cvt.u32.u64 %0, t; }" : "=r"(a) : "l"(p));
    return a;
}
__device__ __forceinline__ void cpasync16(uint32_t dst, const void* src) {
    asm volatile("cp.async.cg.shared.global [%0], [%1], 16;" :: "r"(dst), "l"(src) : "memory");
}
#define CP_COMMIT() asm volatile("cp.async.commit_group;" ::: "memory")
#define CP_WAIT(N)  asm volatile("cp.async.wait_group %0;" :: "n"(N) : "memory")

__device__ __forceinline__ void ldsm4(uint32_t* r, uint32_t addr) {
    asm volatile("ldmatrix.sync.aligned.m8n8.x4.shared.b16 {%0,%1,%2,%3}, [%4];"
        : "=r"(r[0]), "=r"(r[1]), "=r"(r[2]), "=r"(r[3]) : "r"(addr));
}
__device__ __forceinline__ void ldsm2(uint32_t* r, uint32_t addr) {
    asm volatile("ldmatrix.sync.aligned.m8n8.x2.shared.b16 {%0,%1}, [%2];"
        : "=r"(r[0]), "=r"(r[1]) : "r"(addr));
}
__device__ __forceinline__ void mma16816(float* d, const uint32_t* a, const uint32_t* b) {
    asm volatile("mma.sync.aligned.m16n8k16.row.col.f32.f16.f16.f32 "
        "{%0,%1,%2,%3}, {%4,%5,%6,%7}, {%8,%9}, {%0,%1,%2,%3};"
        : "+f"(d[0]), "+f"(d[1]), "+f"(d[2]), "+f"(d[3])
        : "r"(a[0]), "r"(a[1]), "r"(a[2]), "r"(a[3]), "r"(b[0]), "r"(b[1]));
}

__device__ __forceinline__ float sigmoidf_(float x) { return 1.f / (1.f + expf(-x)); }

// One KT=64 chunk of warp-tile MMA: A rows [wm, wm+32), B rows [wn, wn+40).
__device__ __forceinline__ void chunk_mma(uint32_t abuf, uint32_t bbuf,
                                          int wm, int wn, int lane,
                                          float acc[2][5][4]) {
#pragma unroll
    for (int k16 = 0; k16 < 4; ++k16) {
        const int kb = k16 * 16;
        uint32_t a[2][4], b[5][2];
#pragma unroll
        for (int mt = 0; mt < 2; ++mt) {
            uint32_t addr = abuf + (wm + mt * 16 + (lane & 15)) * 144
                          + (kb + ((lane >> 4) << 3)) * 2;
            ldsm4(a[mt], addr);
        }
#pragma unroll
        for (int p = 0; p < 2; ++p) {
            uint32_t r[4];
            uint32_t addr = bbuf
                + (wn + p * 16 + ((lane >> 4) << 3) + (lane & 7)) * 144
                + (kb + (((lane >> 3) & 1) << 3)) * 2;
            ldsm4(r, addr);
            b[p * 2 + 0][0] = r[0]; b[p * 2 + 0][1] = r[1];
            b[p * 2 + 1][0] = r[2]; b[p * 2 + 1][1] = r[3];
        }
        {
            uint32_t addr = bbuf + (wn + 32 + (lane & 7)) * 144
                          + (kb + (((lane >> 3) & 1) << 3)) * 2;
            ldsm2(b[4], addr);
        }
#pragma unroll
        for (int mt = 0; mt < 2; ++mt)
#pragma unroll
            for (int nt = 0; nt < 5; ++nt)
                mma16816(acc[mt][nt], a[mt], b[nt]);
    }
}

// ---------------- pack kernels ----------------
__global__ void split_emb_kernel(const float* __restrict__ emb) {
    int idx = blockIdx.x * blockDim.x + threadIdx.x;
    int stride = gridDim.x * blockDim.x;
    const int total4 = (NN * H) / 4;
    for (int i = idx; i < total4; i += stride) {
        float4 v = reinterpret_cast<const float4*>(emb)[i];
        __half hh[4], hl[4];
        float f[4] = {v.x, v.y, v.z, v.w};
#pragma unroll
        for (int k = 0; k < 4; ++k) {
            hh[k] = __float2half(f[k]);
            hl[k] = __float2half(f[k] - __half2float(hh[k]));
        }
        reinterpret_cast<uint2*>(g_ehi)[i] = *reinterpret_cast<uint2*>(hh);
        reinterpret_cast<uint2*>(g_elo)[i] = *reinterpret_cast<uint2*>(hl);
    }
}

__global__ void pack_w_kernel(
    const float* __restrict__ Wi, const float* __restrict__ bi, const float* __restrict__ Ui,
    const float* __restrict__ Wo, const float* __restrict__ bo, const float* __restrict__ Uo,
    const float* __restrict__ Wu, const float* __restrict__ bu, const float* __restrict__ Uu,
    const float* __restrict__ Wf, const float* __restrict__ bf, const float* __restrict__ Uf)
{
    int idx = blockIdx.x * blockDim.x + threadIdx.x;
    int stride = gridDim.x * blockDim.x;
    if (idx < NCOL) {
        int j = idx / 5, g = idx % 5;
        g_bias[idx] = (g == 0) ? bi[j] : (g == 1) ? bo[j] : (g == 2) ? bu[j] : bf[j];
    }
    for (int e = idx; e < NCOL * KIN; e += stride) {
        int col = e / KIN;
        int k   = e - col * KIN;
        int j = col / 5, g = col % 5;
        float v = 0.f;
        if (k < H) {
            const float* W = (g == 0) ? Wi : (g == 1) ? Wo : (g == 2) ? Wu : Wf;
            v = W[j * H + k];
        } else if (k < 2 * H) {
            int kk = k - H;
            if      (g == 0) v = Ui[j * H + kk];
            else if (g == 1) v = Uo[j * H + kk];
            else if (g == 2) v = Uu[j * H + kk];
            else if (g == 3) v = Uf[j * H + kk];
        } else {
            int kk = k - 2 * H;
            if      (g == 0) v = Ui[H * H + j * H + kk];
            else if (g == 1) v = Uo[H * H + j * H + kk];
            else if (g == 2) v = Uu[H * H + j * H + kk];
            else if (g == 4) v = Uf[H * H + j * H + kk];
        }
        g_B[e] = __float2half(v);
    }
}

// ---------------- main level kernel: 128 nodes x 80 cols, KT=64, 3-stage pipeline ----------------
// Extended K' = 2*KL: split 0 = A_hi * B, split 1 = A_lo * B.
template <bool HASCH>
__global__ void __launch_bounds__(256, 2) hmma_level_kernel(
    int start, int n, float* __restrict__ out)
{
    extern __shared__ char smem[];
    const uint32_t sbase = smem_to_u32(smem);

    const int t    = threadIdx.x;
    const int lane = t & 31;
    const int wid  = t >> 5;
    const int cb   = blockIdx.x;          // 0..15 column blocks (80 cols each)
    const int m0   = blockIdx.y * 128;
    const int gn0  = start + m0;
    const int col0 = cb * 80;

    constexpr int KL  = HASCH ? KIN : H;  // 768 / 256
    constexpr int NCH = 2 * KL / 64;      // 24 / 8

    float acc[2][5][4];
#pragma unroll
    for (int mt = 0; mt < 2; ++mt)
#pragma unroll
        for (int nt = 0; nt < 5; ++nt)
#pragma unroll
            for (int r = 0; r < 4; ++r) acc[mt][nt][r] = 0.f;

    auto load_chunk = [&](int c, int st) {
        const int kk = c * 64;
        const int s  = kk / KL;
        const int k  = kk - s * KL;
        const __half* abase;
        int astride;
        if (!HASCH || k < H) {
            abase = (s == 1 ? g_elo : g_ehi) + (size_t)gn0 * H + k;
            astride = H;
        } else if (k < 2 * H) {
            abase = (s == 1 ? g_hlo : g_hhi) + (size_t)(2 * gn0 + 1) * H + (k - H);
            astride = 2 * H;
        } else {
            abase = (s == 1 ? g_hlo : g_hhi) + (size_t)(2 * gn0 + 2) * H + (k - 2 * H);
            astride = 2 * H;
        }
        const __half* bbase = g_B + (size_t)col0 * KIN + k;
        const uint32_t adst = sbase + st * ASTG;
        const uint32_t bdst = sbase + OFF_BS_MAIN + st * BSTG;
#pragma unroll
        for (int i = 0; i < 7; ++i) {
            int idx = t + i * 256;
            if (idx < 1024) {                       // A: 128 rows x 8 segs
                int row = idx >> 3, seg = idx & 7;
                cpasync16(adst + row * 144 + seg * 16,
                          abase + (size_t)row * astride + seg * 8);
            } else if (idx < 1664) {                // B: 80 rows x 8 segs
                int r2 = idx - 1024;
                int row = r2 >> 3, seg = r2 & 7;
                cpasync16(bdst + row * 144 + seg * 16,
                          bbase + (size_t)row * KIN + seg * 8);
            }
        }
        CP_COMMIT();
    };

    load_chunk(0, 0);
    load_chunk(1, 1);

    const int wm = (wid & 3) * 32;
    const int wn = (wid >> 2) * 40;

    for (int c = 0; c < NCH; ++c) {
        const int st = c % 3;
        if (c == NCH - 1) { CP_WAIT(0); }     // only group c pending
        else              { CP_WAIT(1); }     // groups {c, c+1} pending -> c done
        __syncthreads();                       // all shares visible; all warps past mma(c-1)
        if (c + 2 < NCH) load_chunk(c + 2, (c + 2) % 3);
        chunk_mma(sbase + st * ASTG, sbase + OFF_BS_MAIN + st * BSTG,
                  wm, wn, lane, acc);
    }
    __syncthreads();             // protect stage smem before aliasing as Cs

    // ---- epilogue: frags -> smem C, then gate recombine ----
    float* Cs = reinterpret_cast<float*>(smem);     // [128][84]
#pragma unroll
    for (int mt = 0; mt < 2; ++mt)
#pragma unroll
        for (int nt = 0; nt < 5; ++nt) {
            int m  = wm + mt * 16 + (lane >> 2);
            int nn = wn + nt * 8 + (lane & 3) * 2;
            Cs[m * 84 + nn]           = acc[mt][nt][0];
            Cs[m * 84 + nn + 1]       = acc[mt][nt][1];
            Cs[(m + 8) * 84 + nn]     = acc[mt][nt][2];
            Cs[(m + 8) * 84 + nn + 1] = acc[mt][nt][3];
        }
    __syncthreads();

#pragma unroll
    for (int pass = 0; pass < 8; ++pass) {
        const int task = t + pass * 256;      // 128 nodes x 16 units
        const int m = task >> 4;
        const int u = task & 15;
        if (m0 + m >= n) continue;
        const int gn = gn0 + m;
        const int j  = cb * 16 + u;

        const float* cp = &Cs[m * 84 + u * 5];
        float zi = cp[0] + g_bias[j * 5 + 0];
        float zo = cp[1] + g_bias[j * 5 + 1];
        float zu = cp[2] + g_bias[j * 5 + 2];
        float vi = sigmoidf_(zi);
        float vo = sigmoidf_(zo);
        float vu = tanhf(zu);
        float cv = vi * vu;
        if (HASCH) {
            float zf0 = cp[3] + g_bias[j * 5 + 3];
            float zf1 = cp[4] + g_bias[j * 5 + 4];
            cv += sigmoidf_(zf0) * g_c[(size_t)(2 * gn + 1) * H + j]
                + sigmoidf_(zf1) * g_c[(size_t)(2 * gn + 2) * H + j];
        }
        float h = vo * tanhf(cv);
        __half hh = __float2half(h);
        g_hhi[(size_t)gn * H + j] = hh;
        g_hlo[(size_t)gn * H + j] = __float2half(h - __half2float(hh));
        g_c  [(size_t)gn * H + j] = cv;
        if (out != nullptr && gn == 0) {
            out[j]     = h;
            out[H + j] = cv;
        }
    }
}

// ---------------- small-level kernel: split-K across warps, M tile = 32 ----------------
// 8 warps = 4 K-slices x 2 N-halves. Each warp: 6 of 24 KT=64 chunks (K' = 1536).
__global__ void __launch_bounds__(256) smallk_kernel(int start, int n, float* __restrict__ out)
{
    extern __shared__ char smem[];
    const uint32_t sbase = smem_to_u32(smem);

    const int t    = threadIdx.x;
    const int lane = t & 31;
    const int wid  = t >> 5;
    const int cb   = blockIdx.x;
    const int m0   = blockIdx.y * 32;
    const int gn0  = start + m0;
    const int col0 = cb * 80;

    const int ks = wid >> 1;              // K-slice 0..3
    const int wn = (wid & 1) * 40;        // N half

    constexpr int PER = 6;                // chunks per slice (24/4)

    float acc[2][5][4];
#pragma unroll
    for (int mt = 0; mt < 2; ++mt)
#pragma unroll
        for (int nt = 0; nt < 5; ++nt)
#pragma unroll
            for (int r = 0; r < 4; ++r) acc[mt][nt][r] = 0.f;

    auto load_step = [&](int step, int st) {
#pragma unroll
        for (int i = 0; i < 14; ++i) {            // 4 slices x (256 A + 640 B) = 3584 ops
            int idx = t + i * 256;
            int sl  = idx / 896;
            int rem = idx - sl * 896;
            int c   = sl * PER + step;
            int kp  = c * 64;
            int s   = kp / KIN;
            int k   = kp - s * KIN;
            uint32_t sbuf = sbase + (sl * 2 + st) * SLST;
            if (rem < 256) {                      // A: 32 rows x 8 segs
                int row = rem >> 3, seg = rem & 7;
                const __half* abase;
                int astride;
                if (k < H) {
                    abase = (s == 1 ? g_elo : g_ehi) + (size_t)gn0 * H + k;
                    astride = H;
                } else if (k < 2 * H) {
                    abase = (s == 1 ? g_hlo : g_hhi) + (size_t)(2 * gn0 + 1) * H + (k - H);
                    astride = 2 * H;
                } else {
                    abase = (s == 1 ? g_hlo : g_hhi) + (size_t)(2 * gn0 + 2) * H + (k - 2 * H);
                    astride = 2 * H;
                }
                cpasync16(sbuf + row * 144 + seg * 16,
                          abase + (size_t)row * astride + seg * 8);
            } else {                              // B: 80 rows x 8 segs
                int r2 = rem - 256;
                int row = r2 >> 3, seg = r2 & 7;
                const __half* bbase = g_B + (size_t)col0 * KIN + k;
                cpasync16(sbuf + 32 * 144 + row * 144 + seg * 16,
                          bbase + (size_t)row * KIN + seg * 8);
            }
        }
        CP_COMMIT();
    };

    load_step(0, 0);

    for (int step = 0; step < PER; ++step) {
        const int st = step & 1;
        CP_WAIT(0);
        __syncthreads();
        if (step + 1 < PER) load_step(step + 1, st ^ 1);
        const uint32_t abuf = sbase + (ks * 2 + st) * SLST;
        chunk_mma(abuf, abuf + 32 * 144, 0, wn, lane, acc);
    }
    __syncthreads();

    // ---- reduce 4 K-slices through smem, then gates ----
    float* Cp = reinterpret_cast<float*>(smem);   // [4][32][84] = 43008 B (aliases stages)
#pragma unroll
    for (int mt = 0; mt < 2; ++mt)
#pragma unroll
        for (int nt = 0; nt < 5; ++nt) {
            int m  = mt * 16 + (lane >> 2);
            int nn = wn + nt * 8 + (lane & 3) * 2;
            float* dst = Cp + ks * (32 * 84);
            dst[m * 84 + nn]           = acc[mt][nt][0];
            dst[m * 84 + nn + 1]       = acc[mt][nt][1];
            dst[(m + 8) * 84 + nn]     = acc[mt][nt][2];
            dst[(m + 8) * 84 + nn + 1] = acc[mt][nt][3];
        }
    __syncthreads();

#pragma unroll
    for (int pass = 0; pass < 2; ++pass) {
        const int task = t + pass * 256;          // 32 nodes x 16 units
        const int m = task >> 4;
        const int u = task & 15;
        if (m0 + m >= n) continue;
        const int gn = gn0 + m;
        const int j  = cb * 16 + u;

        float z[5];
#pragma unroll
        for (int g = 0; g < 5; ++g) {
            float s = g_bias[j * 5 + g];
#pragma unroll
            for (int sl = 0; sl < 4; ++sl)
                s += Cp[sl * (32 * 84) + m * 84 + u * 5 + g];
            z[g] = s;
        }
        float vi = sigmoidf_(z[0]);
        float vo = sigmoidf_(z[1]);
        float vu = tanhf(z[2]);
        float cv = vi * vu
                 + sigmoidf_(z[3]) * g_c[(size_t)(2 * gn + 1) * H + j]
                 + sigmoidf_(z[4]) * g_c[(size_t)(2 * gn + 2) * H + j];
        float h = vo * tanhf(cv);
        __half hh = __float2half(h);
        g_hhi[(size_t)gn * H + j] = hh;
        g_hlo[(size_t)gn * H + j] = __float2half(h - __half2float(hh));
        g_c  [(size_t)gn * H + j] = cv;
        if (out != nullptr && gn == 0) {
            out[j]     = h;
            out[H + j] = cv;
        }
    }
}

// ---------------- host launcher ----------------
extern "C" void kernel_launch(void* const* d_in, const int* in_sizes, int n_in,
                              void* d_out, int out_size)
{
    const float* emb = (const float*)d_in[0];
    const float* Wi  = (const float*)d_in[1];
    const float* bi  = (const float*)d_in[2];
    const float* Ui  = (const float*)d_in[3];
    const float* Wo  = (const float*)d_in[4];
    const float* bo  = (const float*)d_in[5];
    const float* Uo  = (const float*)d_in[6];
    const float* Wu  = (const float*)d_in[7];
    const float* bu  = (const float*)d_in[8];
    const float* Uu  = (const float*)d_in[9];
    const float* Wf  = (const float*)d_in[10];
    const float* bf  = (const float*)d_in[11];
    const float* Uf  = (const float*)d_in[12];

    cudaFuncSetAttribute(hmma_level_kernel<false>, cudaFuncAttributeMaxDynamicSharedMemorySize, SMEM_MAIN);
    cudaFuncSetAttribute(hmma_level_kernel<true>,  cudaFuncAttributeMaxDynamicSharedMemorySize, SMEM_MAIN);
    cudaFuncSetAttribute(smallk_kernel,            cudaFuncAttributeMaxDynamicSharedMemorySize, SMEM_SMALL);

    split_emb_kernel<<<2048, 256>>>(emb);
    pack_w_kernel<<<1024, 256>>>(Wi, bi, Ui, Wo, bo, Uo, Wu, bu, Uu, Wf, bf, Uf);

    // leaves: level 15, n = 32768, K' = 512 (no children)
    {
        int n = 1 << (DEPTH - 1);
        int start = n - 1;
        dim3 grid(16, n / 128);
        hmma_level_kernel<false><<<grid, 256, SMEM_MAIN>>>(start, n, nullptr);
    }
    // internal levels bottom-up
    for (int l = DEPTH - 2; l >= 0; --l) {
        int n = 1 << l;
        int start = n - 1;
        float* outp = (l == 0) ? (float*)d_out : nullptr;
        if (n >= 1024) {
            dim3 grid(16, n / 128);
            hmma_level_kernel<true><<<grid, 256, SMEM_MAIN>>>(start, n, outp);
        } else {
            dim3 grid(16, (n + 31) / 32);
            smallk_kernel<<<grid, 256, SMEM_SMALL>>>(start, n, outp);
        }
    }
}

// round 9
// speedup vs baseline: 1.3095x; 1.1286x over previous
#include <cuda_runtime.h>
#include <cuda_fp16.h>
#include <cstdint>
#include <math.h>

#define DEPTH 16
#define NN    65535
#define H     256
#define KIN   768
#define NCOL  1280           // 5 gates * 256 units, col = j*5+g (internal levels)
#define NCOL3 768            // 3 gates * 256 units, col = j*3+g (leaves)

// ---------------- device scratch (no cudaMalloc allowed) ----------------
__device__ __half g_ehi[(size_t)NN * H];
__device__ __half g_elo[(size_t)NN * H];
__device__ __half g_hhi[(size_t)NN * H];
__device__ __half g_hlo[(size_t)NN * H];
__device__ float  g_c  [(size_t)NN * H];
__device__ __half g_B  [(size_t)NCOL * KIN];   // [col][k], internal
__device__ __half g_B3 [(size_t)NCOL3 * H];    // [col][k], leaves (x-part only)
__device__ float  g_bias[NCOL];

// ---------------- smem layouts ----------------
static constexpr int ASTG = 128 * 144;                     // 18432
static constexpr int BSTG = 80 * 144;                      // 11520
static constexpr int OFF_BS_MAIN = 2 * ASTG;               // 36864
static constexpr int SMEM_MAIN   = 2 * (ASTG + BSTG);      // 59904 (x3 CTAs = 179.7KB)
static constexpr int B3STG = 96 * 144;                     // 13824
static constexpr int OFF_BS_LEAF = 2 * ASTG;               // 36864
static constexpr int SMEM_LEAF   = 2 * (ASTG + B3STG);     // 64512
static constexpr int SLST = 32 * 144 + 80 * 144;           // 16128
static constexpr int SMEM_SMALL = 8 * SLST;                // 129024

// ---------------- PTX helpers (baseline sm_80+) ----------------
__device__ __forceinline__ uint32_t smem_to_u32(const void* p) {
    uint32_t a;
    asm("{ .reg .u64 t; cvta.to.shared.u64 t, %1; cvt.u32.u64 %0, t; }" : "=r"(a) : "l"(p));
    return a;
}
__device__ __forceinline__ void cpasync16(uint32_t dst, const void* src) {
    asm volatile("cp.async.cg.shared.global [%0], [%1], 16;" :: "r"(dst), "l"(src) : "memory");
}
#define CP_COMMIT() asm volatile("cp.async.commit_group;" ::: "memory")
#define CP_WAIT(N)  asm volatile("cp.async.wait_group %0;" :: "n"(N) : "memory")

__device__ __forceinline__ void ldsm4(uint32_t* r, uint32_t addr) {
    asm volatile("ldmatrix.sync.aligned.m8n8.x4.shared.b16 {%0,%1,%2,%3}, [%4];"
        : "=r"(r[0]), "=r"(r[1]), "=r"(r[2]), "=r"(r[3]) : "r"(addr));
}
__device__ __forceinline__ void ldsm2(uint32_t* r, uint32_t addr) {
    asm volatile("ldmatrix.sync.aligned.m8n8.x2.shared.b16 {%0,%1}, [%2];"
        : "=r"(r[0]), "=r"(r[1]) : "r"(addr));
}
__device__ __forceinline__ void mma16816(float* d, const uint32_t* a, const uint32_t* b) {
    asm volatile("mma.sync.aligned.m16n8k16.row.col.f32.f16.f16.f32 "
        "{%0,%1,%2,%3}, {%4,%5,%6,%7}, {%8,%9}, {%0,%1,%2,%3};"
        : "+f"(d[0]), "+f"(d[1]), "+f"(d[2]), "+f"(d[3])
        : "r"(a[0]), "r"(a[1]), "r"(a[2]), "r"(a[3]), "r"(b[0]), "r"(b[1]));
}

__device__ __forceinline__ float sigmoidf_(float x) { return 1.f / (1.f + expf(-x)); }

// KT=64 chunk: A rows [wm,wm+32), B rows [wn,wn+40) (5 n-tiles, ldsm2 tail).
__device__ __forceinline__ void chunk_mma5(uint32_t abuf, uint32_t bbuf,
                                           int wm, int wn, int lane,
                                           float acc[2][5][4]) {
#pragma unroll
    for (int k16 = 0; k16 < 4; ++k16) {
        const int kb = k16 * 16;
        uint32_t a[2][4], b[5][2];
#pragma unroll
        for (int mt = 0; mt < 2; ++mt) {
            uint32_t addr = abuf + (wm + mt * 16 + (lane & 15)) * 144
                          + (kb + ((lane >> 4) << 3)) * 2;
            ldsm4(a[mt], addr);
        }
#pragma unroll
        for (int p = 0; p < 2; ++p) {
            uint32_t r[4];
            uint32_t addr = bbuf
                + (wn + p * 16 + ((lane >> 4) << 3) + (lane & 7)) * 144
                + (kb + (((lane >> 3) & 1) << 3)) * 2;
            ldsm4(r, addr);
            b[p * 2 + 0][0] = r[0]; b[p * 2 + 0][1] = r[1];
            b[p * 2 + 1][0] = r[2]; b[p * 2 + 1][1] = r[3];
        }
        {
            uint32_t addr = bbuf + (wn + 32 + (lane & 7)) * 144
                          + (kb + (((lane >> 3) & 1) << 3)) * 2;
            ldsm2(b[4], addr);
        }
#pragma unroll
        for (int mt = 0; mt < 2; ++mt)
#pragma unroll
            for (int nt = 0; nt < 5; ++nt)
                mma16816(acc[mt][nt], a[mt], b[nt]);
    }
}

// KT=64 chunk: A rows [wm,wm+32), B rows [wn,wn+48) (6 n-tiles).
__device__ __forceinline__ void chunk_mma6(uint32_t abuf, uint32_t bbuf,
                                           int wm, int wn, int lane,
                                           float acc[2][6][4]) {
#pragma unroll
    for (int k16 = 0; k16 < 4; ++k16) {
        const int kb = k16 * 16;
        uint32_t a[2][4], b[6][2];
#pragma unroll
        for (int mt = 0; mt < 2; ++mt) {
            uint32_t addr = abuf + (wm + mt * 16 + (lane & 15)) * 144
                          + (kb + ((lane >> 4) << 3)) * 2;
            ldsm4(a[mt], addr);
        }
#pragma unroll
        for (int p = 0; p < 3; ++p) {
            uint32_t r[4];
            uint32_t addr = bbuf
                + (wn + p * 16 + ((lane >> 4) << 3) + (lane & 7)) * 144
                + (kb + (((lane >> 3) & 1) << 3)) * 2;
            ldsm4(r, addr);
            b[p * 2 + 0][0] = r[0]; b[p * 2 + 0][1] = r[1];
            b[p * 2 + 1][0] = r[2]; b[p * 2 + 1][1] = r[3];
        }
#pragma unroll
        for (int mt = 0; mt < 2; ++mt)
#pragma unroll
            for (int nt = 0; nt < 6; ++nt)
                mma16816(acc[mt][nt], a[mt], b[nt]);
    }
}

// ---------------- pack kernels ----------------
__global__ void split_emb_kernel(const float* __restrict__ emb) {
    int idx = blockIdx.x * blockDim.x + threadIdx.x;
    int stride = gridDim.x * blockDim.x;
    const int total4 = (NN * H) / 4;
    for (int i = idx; i < total4; i += stride) {
        float4 v = reinterpret_cast<const float4*>(emb)[i];
        __half hh[4], hl[4];
        float f[4] = {v.x, v.y, v.z, v.w};
#pragma unroll
        for (int k = 0; k < 4; ++k) {
            hh[k] = __float2half(f[k]);
            hl[k] = __float2half(f[k] - __half2float(hh[k]));
        }
        reinterpret_cast<uint2*>(g_ehi)[i] = *reinterpret_cast<uint2*>(hh);
        reinterpret_cast<uint2*>(g_elo)[i] = *reinterpret_cast<uint2*>(hl);
    }
}

__global__ void pack_w_kernel(
    const float* __restrict__ Wi, const float* __restrict__ bi, const float* __restrict__ Ui,
    const float* __restrict__ Wo, const float* __restrict__ bo, const float* __restrict__ Uo,
    const float* __restrict__ Wu, const float* __restrict__ bu, const float* __restrict__ Uu,
    const float* __restrict__ Wf, const float* __restrict__ bf, const float* __restrict__ Uf)
{
    int idx = blockIdx.x * blockDim.x + threadIdx.x;
    int stride = gridDim.x * blockDim.x;
    if (idx < NCOL) {
        int j = idx / 5, g = idx % 5;
        g_bias[idx] = (g == 0) ? bi[j] : (g == 1) ? bo[j] : (g == 2) ? bu[j] : bf[j];
    }
    for (int e = idx; e < NCOL * KIN; e += stride) {
        int col = e / KIN;
        int k   = e - col * KIN;
        int j = col / 5, g = col % 5;
        float v = 0.f;
        if (k < H) {
            const float* W = (g == 0) ? Wi : (g == 1) ? Wo : (g == 2) ? Wu : Wf;
            v = W[j * H + k];
        } else if (k < 2 * H) {
            int kk = k - H;
            if      (g == 0) v = Ui[j * H + kk];
            else if (g == 1) v = Uo[j * H + kk];
            else if (g == 2) v = Uu[j * H + kk];
            else if (g == 3) v = Uf[j * H + kk];
        } else {
            int kk = k - 2 * H;
            if      (g == 0) v = Ui[H * H + j * H + kk];
            else if (g == 1) v = Uo[H * H + j * H + kk];
            else if (g == 2) v = Uu[H * H + j * H + kk];
            else if (g == 4) v = Uf[H * H + j * H + kk];
        }
        g_B[e] = __float2half(v);
    }
    // leaf 3-gate pack: col = j*3+g, g in {i,o,u}, k in [0,256)
    for (int e = idx; e < NCOL3 * H; e += stride) {
        int col = e / H;
        int k   = e - col * H;
        int j = col / 3, g = col % 3;
        const float* W = (g == 0) ? Wi : (g == 1) ? Wo : Wu;
        g_B3[e] = __float2half(W[j * H + k]);
    }
}

// ---------------- internal level kernel: 128 x 80, KT=64, 2-stage, 3 CTAs/SM ----------------
// Extended K' = 2*KIN: split 0 = A_hi * B, split 1 = A_lo * B. NCH = 24.
__global__ void __launch_bounds__(256, 3) hmma_level_kernel(
    int start, int n, float* __restrict__ out)
{
    extern __shared__ char smem[];
    const uint32_t sbase = smem_to_u32(smem);

    const int t    = threadIdx.x;
    const int lane = t & 31;
    const int wid  = t >> 5;
    const int cb   = blockIdx.x;          // 0..15 (80-col blocks)
    const int m0   = blockIdx.y * 128;
    const int gn0  = start + m0;
    const int col0 = cb * 80;

    constexpr int NCH = 24;

    // A-section base pointers (uniform; selected per chunk without local arrays)
    const __half* e_hi = g_ehi + (size_t)gn0 * H;
    const __half* e_lo = g_elo + (size_t)gn0 * H;
    const __half* c1hi = g_hhi + (size_t)(2 * gn0 + 1) * H;
    const __half* c1lo = g_hlo + (size_t)(2 * gn0 + 1) * H;
    const __half* c2hi = g_hhi + (size_t)(2 * gn0 + 2) * H;
    const __half* c2lo = g_hlo + (size_t)(2 * gn0 + 2) * H;

    float acc[2][5][4];
#pragma unroll
    for (int mt = 0; mt < 2; ++mt)
#pragma unroll
        for (int nt = 0; nt < 5; ++nt)
#pragma unroll
            for (int r = 0; r < 4; ++r) acc[mt][nt][r] = 0.f;

    auto load_chunk = [&](int c, int st) {
        const int sp  = (c >= 12);
        const int cc  = c - (sp ? 12 : 0);
        const int sec = cc >> 2;
        const int kof = (cc & 3) << 6;
        const __half* ab = (sec == 0) ? (sp ? e_lo : e_hi)
                         : (sec == 1) ? (sp ? c1lo : c1hi)
                                      : (sp ? c2lo : c2hi);
        const int astr = (sec == 0) ? H : 2 * H;
        const __half* bbase = g_B + (size_t)col0 * KIN + cc * 64;
        const uint32_t adst = sbase + st * ASTG;
        const uint32_t bdst = sbase + OFF_BS_MAIN + st * BSTG;
#pragma unroll
        for (int i = 0; i < 7; ++i) {
            int idx = t + i * 256;
            if (idx < 1024) {                       // A: 128 rows x 8 segs
                int row = idx >> 3, seg = idx & 7;
                cpasync16(adst + row * 144 + seg * 16,
                          ab + (size_t)row * astr + kof + seg * 8);
            } else if (idx < 1664) {                // B: 80 rows x 8 segs
                int r2 = idx - 1024;
                int row = r2 >> 3, seg = r2 & 7;
                cpasync16(bdst + row * 144 + seg * 16,
                          bbase + (size_t)row * KIN + seg * 8);
            }
        }
        CP_COMMIT();
    };

    load_chunk(0, 0);

    const int wm = (wid & 3) * 32;
    const int wn = (wid >> 2) * 40;

    for (int c = 0; c < NCH; ++c) {
        const int st = c & 1;
        CP_WAIT(0);
        __syncthreads();
        if (c + 1 < NCH) load_chunk(c + 1, st ^ 1);
        chunk_mma5(sbase + st * ASTG, sbase + OFF_BS_MAIN + st * BSTG,
                   wm, wn, lane, acc);
    }
    __syncthreads();

    // ---- epilogue: frags -> smem C, then gate recombine ----
    float* Cs = reinterpret_cast<float*>(smem);     // [128][84]
#pragma unroll
    for (int mt = 0; mt < 2; ++mt)
#pragma unroll
        for (int nt = 0; nt < 5; ++nt) {
            int m  = wm + mt * 16 + (lane >> 2);
            int nn = wn + nt * 8 + (lane & 3) * 2;
            Cs[m * 84 + nn]           = acc[mt][nt][0];
            Cs[m * 84 + nn + 1]       = acc[mt][nt][1];
            Cs[(m + 8) * 84 + nn]     = acc[mt][nt][2];
            Cs[(m + 8) * 84 + nn + 1] = acc[mt][nt][3];
        }
    __syncthreads();

#pragma unroll
    for (int pass = 0; pass < 8; ++pass) {
        const int task = t + pass * 256;      // 128 nodes x 16 units
        const int m = task >> 4;
        const int u = task & 15;
        if (m0 + m >= n) continue;
        const int gn = gn0 + m;
        const int j  = cb * 16 + u;

        const float* cp = &Cs[m * 84 + u * 5];
        float zi = cp[0] + g_bias[j * 5 + 0];
        float zo = cp[1] + g_bias[j * 5 + 1];
        float zu = cp[2] + g_bias[j * 5 + 2];
        float zf0 = cp[3] + g_bias[j * 5 + 3];
        float zf1 = cp[4] + g_bias[j * 5 + 4];
        float vi = sigmoidf_(zi);
        float vo = sigmoidf_(zo);
        float vu = tanhf(zu);
        float cv = vi * vu
                 + sigmoidf_(zf0) * g_c[(size_t)(2 * gn + 1) * H + j]
                 + sigmoidf_(zf1) * g_c[(size_t)(2 * gn + 2) * H + j];
        float h = vo * tanhf(cv);
        __half hh = __float2half(h);
        g_hhi[(size_t)gn * H + j] = hh;
        g_hlo[(size_t)gn * H + j] = __float2half(h - __half2float(hh));
        g_c  [(size_t)gn * H + j] = cv;
        if (out != nullptr && gn == 0) {
            out[j]     = h;
            out[H + j] = cv;
        }
    }
}

// ---------------- leaf kernel: 128 nodes x 96 cols (32 units x 3 gates), K'=512 ----------------
__global__ void __launch_bounds__(256, 2) leaf_kernel(int start, int n)
{
    extern __shared__ char smem[];
    const uint32_t sbase = smem_to_u32(smem);

    const int t    = threadIdx.x;
    const int lane = t & 31;
    const int wid  = t >> 5;
    const int cb   = blockIdx.x;          // 0..7 (96-col blocks)
    const int m0   = blockIdx.y * 128;
    const int gn0  = start + m0;
    const int col0 = cb * 96;

    constexpr int NCH = 8;                // 2 splits x 256 / 64

    const __half* e_hi = g_ehi + (size_t)gn0 * H;
    const __half* e_lo = g_elo + (size_t)gn0 * H;

    float acc[2][6][4];
#pragma unroll
    for (int mt = 0; mt < 2; ++mt)
#pragma unroll
        for (int nt = 0; nt < 6; ++nt)
#pragma unroll
            for (int r = 0; r < 4; ++r) acc[mt][nt][r] = 0.f;

    auto load_chunk = [&](int c, int st) {
        const int sp  = (c >= 4);
        const int kof = (c & 3) << 6;
        const __half* ab = sp ? e_lo : e_hi;
        const __half* bbase = g_B3 + (size_t)col0 * H + kof;
        const uint32_t adst = sbase + st * ASTG;
        const uint32_t bdst = sbase + OFF_BS_LEAF + st * B3STG;
#pragma unroll
        for (int i = 0; i < 7; ++i) {
            int idx = t + i * 256;
            if (idx < 1024) {                       // A: 128 rows x 8 segs
                int row = idx >> 3, seg = idx & 7;
                cpasync16(adst + row * 144 + seg * 16,
                          ab + (size_t)row * H + kof + seg * 8);
            } else if (idx < 1792) {                // B3: 96 rows x 8 segs
                int r2 = idx - 1024;
                int row = r2 >> 3, seg = r2 & 7;
                cpasync16(bdst + row * 144 + seg * 16,
                          bbase + (size_t)row * H + seg * 8);
            }
        }
        CP_COMMIT();
    };

    load_chunk(0, 0);

    const int wm = (wid & 3) * 32;
    const int wn = (wid >> 2) * 48;

    for (int c = 0; c < NCH; ++c) {
        const int st = c & 1;
        CP_WAIT(0);
        __syncthreads();
        if (c + 1 < NCH) load_chunk(c + 1, st ^ 1);
        chunk_mma6(sbase + st * ASTG, sbase + OFF_BS_LEAF + st * B3STG,
                   wm, wn, lane, acc);
    }
    __syncthreads();

    // ---- epilogue ----
    float* Cs = reinterpret_cast<float*>(smem);     // [128][100]
#pragma unroll
    for (int mt = 0; mt < 2; ++mt)
#pragma unroll
        for (int nt = 0; nt < 6; ++nt) {
            int m  = wm + mt * 16 + (lane >> 2);
            int nn = wn + nt * 8 + (lane & 3) * 2;
            Cs[m * 100 + nn]           = acc[mt][nt][0];
            Cs[m * 100 + nn + 1]       = acc[mt][nt][1];
            Cs[(m + 8) * 100 + nn]     = acc[mt][nt][2];
            Cs[(m + 8) * 100 + nn + 1] = acc[mt][nt][3];
        }
    __syncthreads();

#pragma unroll
    for (int pass = 0; pass < 16; ++pass) {
        const int task = t + pass * 256;      // 128 nodes x 32 units
        const int m = task >> 5;
        const int u = task & 31;
        if (m0 + m >= n) continue;
        const int gn = gn0 + m;
        const int j  = cb * 32 + u;

        const float* cp = &Cs[m * 100 + u * 3];
        float zi = cp[0] + g_bias[j * 5 + 0];
        float zo = cp[1] + g_bias[j * 5 + 1];
        float zu = cp[2] + g_bias[j * 5 + 2];
        float vi = sigmoidf_(zi);
        float vo = sigmoidf_(zo);
        float vu = tanhf(zu);
        float cv = vi * vu;
        float h = vo * tanhf(cv);
        __half hh = __float2half(h);
        g_hhi[(size_t)gn * H + j] = hh;
        g_hlo[(size_t)gn * H + j] = __float2half(h - __half2float(hh));
        g_c  [(size_t)gn * H + j] = cv;
    }
}

// ---------------- small-level kernel: split-K across warps, M tile = 32 ----------------
// 8 warps = 4 K-slices x 2 N-halves. Each warp: 6 of 24 KT=64 chunks (K' = 1536).
__global__ void __launch_bounds__(256) smallk_kernel(int start, int n, float* __restrict__ out)
{
    extern __shared__ char smem[];
    const uint32_t sbase = smem_to_u32(smem);

    const int t    = threadIdx.x;
    const int lane = t & 31;
    const int wid  = t >> 5;
    const int cb   = blockIdx.x;
    const int m0   = blockIdx.y * 32;
    const int gn0  = start + m0;
    const int col0 = cb * 80;

    const int ks = wid >> 1;              // K-slice 0..3
    const int wn = (wid & 1) * 40;        // N half

    constexpr int PER = 6;                // chunks per slice (24/4)

    float acc[2][5][4];
#pragma unroll
    for (int mt = 0; mt < 2; ++mt)
#pragma unroll
        for (int nt = 0; nt < 5; ++nt)
#pragma unroll
            for (int r = 0; r < 4; ++r) acc[mt][nt][r] = 0.f;

    auto load_step = [&](int step, int st) {
#pragma unroll
        for (int i = 0; i < 14; ++i) {            // 4 slices x (256 A + 640 B) = 3584 ops
            int idx = t + i * 256;
            int sl  = idx / 896;
            int rem = idx - sl * 896;
            int c   = sl * PER + step;
            int kp  = c * 64;
            int s   = kp / KIN;
            int k   = kp - s * KIN;
            uint32_t sbuf = sbase + (sl * 2 + st) * SLST;
            if (rem < 256) {                      // A: 32 rows x 8 segs
                int row = rem >> 3, seg = rem & 7;
                const __half* abase;
                int astride;
                if (k < H) {
                    abase = (s == 1 ? g_elo : g_ehi) + (size_t)gn0 * H + k;
                    astride = H;
                } else if (k < 2 * H) {
                    abase = (s == 1 ? g_hlo : g_hhi) + (size_t)(2 * gn0 + 1) * H + (k - H);
                    astride = 2 * H;
                } else {
                    abase = (s == 1 ? g_hlo : g_hhi) + (size_t)(2 * gn0 + 2) * H + (k - 2 * H);
                    astride = 2 * H;
                }
                cpasync16(sbuf + row * 144 + seg * 16,
                          abase + (size_t)row * astride + seg * 8);
            } else {                              // B: 80 rows x 8 segs
                int r2 = rem - 256;
                int row = r2 >> 3, seg = r2 & 7;
                const __half* bbase = g_B + (size_t)col0 * KIN + k;
                cpasync16(sbuf + 32 * 144 + row * 144 + seg * 16,
                          bbase + (size_t)row * KIN + seg * 8);
            }
        }
        CP_COMMIT();
    };

    load_step(0, 0);

    for (int step = 0; step < PER; ++step) {
        const int st = step & 1;
        CP_WAIT(0);
        __syncthreads();
        if (step + 1 < PER) load_step(step + 1, st ^ 1);
        const uint32_t abuf = sbase + (ks * 2 + st) * SLST;
        chunk_mma5(abuf, abuf + 32 * 144, 0, wn, lane, acc);
    }
    __syncthreads();

    // ---- reduce 4 K-slices through smem, then gates ----
    float* Cp = reinterpret_cast<float*>(smem);   // [4][32][84] = 43008 B (aliases stages)
#pragma unroll
    for (int mt = 0; mt < 2; ++mt)
#pragma unroll
        for (int nt = 0; nt < 5; ++nt) {
            int m  = mt * 16 + (lane >> 2);
            int nn = wn + nt * 8 + (lane & 3) * 2;
            float* dst = Cp + ks * (32 * 84);
            dst[m * 84 + nn]           = acc[mt][nt][0];
            dst[m * 84 + nn + 1]       = acc[mt][nt][1];
            dst[(m + 8) * 84 + nn]     = acc[mt][nt][2];
            dst[(m + 8) * 84 + nn + 1] = acc[mt][nt][3];
        }
    __syncthreads();

#pragma unroll
    for (int pass = 0; pass < 2; ++pass) {
        const int task = t + pass * 256;          // 32 nodes x 16 units
        const int m = task >> 4;
        const int u = task & 15;
        if (m0 + m >= n) continue;
        const int gn = gn0 + m;
        const int j  = cb * 16 + u;

        float z[5];
#pragma unroll
        for (int g = 0; g < 5; ++g) {
            float s = g_bias[j * 5 + g];
#pragma unroll
            for (int sl = 0; sl < 4; ++sl)
                s += Cp[sl * (32 * 84) + m * 84 + u * 5 + g];
            z[g] = s;
        }
        float vi = sigmoidf_(z[0]);
        float vo = sigmoidf_(z[1]);
        float vu = tanhf(z[2]);
        float cv = vi * vu
                 + sigmoidf_(z[3]) * g_c[(size_t)(2 * gn + 1) * H + j]
                 + sigmoidf_(z[4]) * g_c[(size_t)(2 * gn + 2) * H + j];
        float h = vo * tanhf(cv);
        __half hh = __float2half(h);
        g_hhi[(size_t)gn * H + j] = hh;
        g_hlo[(size_t)gn * H + j] = __float2half(h - __half2float(hh));
        g_c  [(size_t)gn * H + j] = cv;
        if (out != nullptr && gn == 0) {
            out[j]     = h;
            out[H + j] = cv;
        }
    }
}

// ---------------- host launcher ----------------
extern "C" void kernel_launch(void* const* d_in, const int* in_sizes, int n_in,
                              void* d_out, int out_size)
{
    const float* emb = (const float*)d_in[0];
    const float* Wi  = (const float*)d_in[1];
    const float* bi  = (const float*)d_in[2];
    const float* Ui  = (const float*)d_in[3];
    const float* Wo  = (const float*)d_in[4];
    const float* bo  = (const float*)d_in[5];
    const float* Uo  = (const float*)d_in[6];
    const float* Wu  = (const float*)d_in[7];
    const float* bu  = (const float*)d_in[8];
    const float* Uu  = (const float*)d_in[9];
    const float* Wf  = (const float*)d_in[10];
    const float* bf  = (const float*)d_in[11];
    const float* Uf  = (const float*)d_in[12];

    cudaFuncSetAttribute(hmma_level_kernel, cudaFuncAttributeMaxDynamicSharedMemorySize, SMEM_MAIN);
    cudaFuncSetAttribute(leaf_kernel,       cudaFuncAttributeMaxDynamicSharedMemorySize, SMEM_LEAF);
    cudaFuncSetAttribute(smallk_kernel,     cudaFuncAttributeMaxDynamicSharedMemorySize, SMEM_SMALL);

    split_emb_kernel<<<2048, 256>>>(emb);
    pack_w_kernel<<<1024, 256>>>(Wi, bi, Ui, Wo, bo, Uo, Wu, bu, Uu, Wf, bf, Uf);

    // leaves: level 15, n = 32768, 3 gates only
    {
        int n = 1 << (DEPTH - 1);
        int start = n - 1;
        dim3 grid(8, n / 128);
        leaf_kernel<<<grid, 256, SMEM_LEAF>>>(start, n);
    }
    // internal levels bottom-up
    for (int l = DEPTH - 2; l >= 0; --l) {
        int n = 1 << l;
        int start = n - 1;
        float* outp = (l == 0) ? (float*)d_out : nullptr;
        if (n >= 1024) {
            dim3 grid(16, n / 128);
            hmma_level_kernel<<<grid, 256, SMEM_MAIN>>>(start, n, outp);
        } else {
            dim3 grid(16, (n + 31) / 32);
            smallk_kernel<<<grid, 256, SMEM_SMALL>>>(start, n, outp);
        }
    }
}